// round 1
// baseline (speedup 1.0000x reference)
#include <cuda_runtime.h>

#define BB 128
#define TT 1024
#define CC 128
#define LL 128
#define SS 257           // 2L+1
#define EPSF 1e-7f
#define NEGF -1e30f

__global__ __launch_bounds__(288, 1)
void ctc_loss_kernel(const int* __restrict__ y_true,
                     const float* __restrict__ y_pred,
                     const int* __restrict__ input_len,
                     const int* __restrict__ label_len,
                     float* __restrict__ out)
{
    // alpha double buffer with 2-slot NEG pad in front: state s lives at [s+2]
    __shared__ float alpha[2][SS + 2];
    __shared__ float lp[2][CC];     // log(y_pred[t] + eps) row, double buffered

    const int b   = blockIdx.x;
    const int tid = threadIdx.x;
    const int s   = tid;            // state index for tid < SS

    int Tin = input_len[b];
    if (Tin > TT) Tin = TT;
    if (Tin < 0)  Tin = 0;

    // Per-thread extended label + skip-allowed flag (registers, computed once).
    // ext[s] = blank (C-1) for even s, y_true[s/2] for odd s.
    // skip allowed iff s>=2, ext[s]!=blank (odd s only), ext[s]!=ext[s-2].
    int  ext_s = CC - 1;
    bool skip  = false;
    if (s < SS) {
        if (s & 1) {
            ext_s = y_true[b * LL + (s >> 1)];
            if (s >= 3) {
                int prev = y_true[b * LL + ((s - 2) >> 1)];
                skip = (ext_s != prev);
            }
        }
        alpha[0][s + 2] = (s == 0) ? 0.0f : NEGF;
        alpha[1][s + 2] = NEGF;
    }
    if (tid < 2) { alpha[0][tid] = NEGF; alpha[1][tid] = NEGF; }

    const float* __restrict__ yp_b = y_pred + (size_t)b * TT * CC;

    if (tid < CC && Tin > 0)
        lp[0][tid] = __logf(__ldg(&yp_b[tid]) + EPSF);
    __syncthreads();

    int cur = 0;
    for (int t = 0; t < Tin; ++t) {
        const int par = t & 1;

        // Prefetch next emission row early (hide DRAM/L2 latency under compute)
        float pnext = 0.0f;
        const bool pre = (tid < CC) && (t + 1 < Tin);
        if (pre) pnext = __ldg(&yp_b[(size_t)(t + 1) * CC + tid]);

        if (s < SS) {
            float a  = alpha[cur][s + 2];
            float a1 = alpha[cur][s + 1];
            float a2 = skip ? alpha[cur][s] : NEGF;
            float m  = fmaxf(fmaxf(a, a1), a2);
            // All args <= 0; __expf(-huge) -> 0, no NaN paths.
            float sum = __expf(a - m) + __expf(a1 - m) + __expf(a2 - m);
            alpha[cur ^ 1][s + 2] = lp[par][ext_s] + m + __logf(sum);
        }

        if (pre) lp[par ^ 1][tid] = __logf(pnext + EPSF);

        __syncthreads();
        cur ^= 1;
    }

    if (tid == 0) {
        int lab = label_len[b];
        if (lab < 0)  lab = 0;
        if (lab > LL) lab = LL;
        float aL = alpha[cur][2 * lab + 2];          // ends at final blank
        int ip = 2 * lab - 1; if (ip < 0) ip = 0;    // or final label
        float aP = alpha[cur][ip + 2];
        float m  = fmaxf(aL, aP);
        out[b] = -(m + __logf(__expf(aL - m) + __expf(aP - m)));
    }
}

extern "C" void kernel_launch(void* const* d_in, const int* in_sizes, int n_in,
                              void* d_out, int out_size) {
    // Identify inputs by size; ties (input_len vs label_len, both B) resolved by
    // metadata order: y_true, y_pred, input_len, label_len.
    const int*   y_true    = nullptr;
    const float* y_pred    = nullptr;
    const int*   input_len = nullptr;
    const int*   label_len = nullptr;
    for (int i = 0; i < n_in; ++i) {
        if (in_sizes[i] == BB * TT * CC)      y_pred = (const float*)d_in[i];
        else if (in_sizes[i] == BB * LL)      y_true = (const int*)d_in[i];
        else if (in_sizes[i] == BB) {
            if (!input_len) input_len = (const int*)d_in[i];
            else            label_len = (const int*)d_in[i];
        }
    }
    ctc_loss_kernel<<<BB, 288>>>(y_true, y_pred, input_len, label_len, (float*)d_out);
}

// round 2
// speedup vs baseline: 1.7376x; 1.7376x over previous
#include <cuda_runtime.h>

#define BB 128
#define TT 1024
#define CC 128
#define LL 128
#define SS 257           // 2L+1
#define EPSF 1e-7f
#define NEGF -1e30f
#define LN2F 0.69314718055994530942f
#define STAGES 8
#define PF 6             // prefetch distance (rows in flight)

__device__ __forceinline__ float ex2f(float x) {
    float y; asm("ex2.approx.ftz.f32 %0, %1;" : "=f"(y) : "f"(x)); return y;
}
__device__ __forceinline__ float lg2f(float x) {
    float y; asm("lg2.approx.f32 %0, %1;" : "=f"(y) : "f"(x)); return y;
}
__device__ __forceinline__ void cp16(void* smem_dst, const void* gmem_src) {
    unsigned saddr = (unsigned)__cvta_generic_to_shared(smem_dst);
    asm volatile("cp.async.cg.shared.global [%0], [%1], 16;"
                 :: "r"(saddr), "l"(gmem_src) : "memory");
}

__global__ __launch_bounds__(288, 1)
void ctc_loss_kernel(const int* __restrict__ y_true,
                     const float* __restrict__ y_pred,
                     const int* __restrict__ input_len,
                     const int* __restrict__ label_len,
                     float* __restrict__ out)
{
    // alpha (log2 domain) double buffer, 2-slot NEG pad in front: state s at [s+2]
    __shared__ float alpha[2][SS + 2];
    __shared__ __align__(16) float ring[STAGES][CC];  // raw prob rows, cp.async ring

    const int b   = blockIdx.x;
    const int tid = threadIdx.x;
    const int s   = tid;

    int Tin = input_len[b];
    if (Tin > TT) Tin = TT;
    if (Tin < 0)  Tin = 0;

    // Per-thread extended label + skip flag.
    int  ext_s = CC - 1;          // blank
    bool skip  = false;
    if (s < SS) {
        if (s & 1) {
            ext_s = y_true[b * LL + (s >> 1)];
            if (s >= 3) skip = (ext_s != y_true[b * LL + ((s - 2) >> 1)]);
        }
        alpha[0][s + 2] = (s == 0) ? 0.0f : NEGF;
        alpha[1][s + 2] = NEGF;
    }
    if (tid < 2) { alpha[0][tid] = NEGF; alpha[1][tid] = NEGF; }

    const float* __restrict__ yp_b = y_pred + (size_t)b * TT * CC;

    // Prologue: prefetch rows 0..PF-1, one commit group per row.
    if (tid < 32) {
        #pragma unroll
        for (int r = 0; r < PF; ++r) {
            if (r < Tin) cp16(&ring[r][tid * 4], yp_b + (size_t)r * CC + tid * 4);
            asm volatile("cp.async.commit_group;" ::: "memory");
        }
    }

    int cur = 0;
    for (int t = 0; t < Tin; ++t) {
        if (tid < 32) {
            int rf = t + PF;
            if (rf < Tin)
                cp16(&ring[rf & (STAGES - 1)][tid * 4],
                     yp_b + (size_t)rf * CC + tid * 4);
            asm volatile("cp.async.commit_group;" ::: "memory");
            asm volatile("cp.async.wait_group %0;" :: "n"(PF - 1) : "memory");
        }
        // One barrier per step: publishes previous alpha AND row t of the ring.
        __syncthreads();

        if (s < SS) {
            float p  = ring[t & (STAGES - 1)][ext_s] + EPSF;
            float lp = lg2f(p);                       // log2 emission
            float a  = alpha[cur][s + 2];
            float a1 = alpha[cur][s + 1];
            float a2 = skip ? alpha[cur][s] : NEGF;
            float m  = fmaxf(fmaxf(a, a1), a2);
            float sum = ex2f(a - m) + ex2f(a1 - m) + ex2f(a2 - m);
            alpha[cur ^ 1][s + 2] = lp + m + lg2f(sum);
        }
        cur ^= 1;
    }
    __syncthreads();   // publish final alpha

    if (tid == 0) {
        int lab = label_len[b];
        if (lab < 0)  lab = 0;
        if (lab > LL) lab = LL;
        float aL = alpha[cur][2 * lab + 2];
        int ip = 2 * lab - 1; if (ip < 0) ip = 0;
        float aP = alpha[cur][ip + 2];
        float m  = fmaxf(aL, aP);
        // convert log2 -> nats at the very end
        out[b] = -LN2F * (m + lg2f(ex2f(aL - m) + ex2f(aP - m)));
    }
}

extern "C" void kernel_launch(void* const* d_in, const int* in_sizes, int n_in,
                              void* d_out, int out_size) {
    const int*   y_true    = nullptr;
    const float* y_pred    = nullptr;
    const int*   input_len = nullptr;
    const int*   label_len = nullptr;
    for (int i = 0; i < n_in; ++i) {
        if (in_sizes[i] == BB * TT * CC)      y_pred = (const float*)d_in[i];
        else if (in_sizes[i] == BB * LL)      y_true = (const int*)d_in[i];
        else if (in_sizes[i] == BB) {
            if (!input_len) input_len = (const int*)d_in[i];
            else            label_len = (const int*)d_in[i];
        }
    }
    ctc_loss_kernel<<<BB, 288>>>(y_true, y_pred, input_len, label_len, (float*)d_out);
}